// round 7
// baseline (speedup 1.0000x reference)
#include <cuda_runtime.h>
#include <cuda_bf16.h>

#define NB 32
#define TC 256
#define NVOCAB 100
#define ND 384
#define NWARPS 16
#define NTILES 4
#define MAXT 2048
#define FB 4            // frames per warp per group
#define RWIN 32         // |t-center|>RWIN => z>=8 => rel contribution < 1e-13
#define WMAX 80         // max chars in union window

__device__ float g_center[NB][TC];
__device__ float g_invsig[NB][TC];
__device__ float g_wfac[NB][TC];
__device__ int   g_row[NB][TC];
__device__ int   g_totdur[NB];
__device__ int   g_fidx[NB][MAXT];

__global__ void ge_prep_kernel(const int* __restrict__ text,
                               const int* __restrict__ durs) {
    __shared__ int s[TC];
    int b = blockIdx.x, c = threadIdx.x;
    int d = durs[b * TC + c];
    s[c] = d;
    __syncthreads();
    #pragma unroll
    for (int off = 1; off < TC; off <<= 1) {
        int v = (c >= off) ? s[c - off] : 0;
        __syncthreads();
        s[c] += v;
        __syncthreads();
    }
    int incl = s[c];
    int start = incl - d;
    float df = (float)d;
    float sig = df * 0.5f + 1e-6f;
    float is = 1.0f / sig;
    g_center[b][c] = (float)start + df * 0.5f;
    g_invsig[b][c] = is;
    g_wfac[b][c]   = 0.3989422804014327f * is;
    g_row[b][c]    = text[b * TC + c];
    for (int f = start; f < incl; f++) g_fidx[b][f] = c;
    if (c == TC - 1) g_totdur[b] = incl;
}

__device__ __forceinline__ void fma2(unsigned long long& acc,
                                     unsigned long long a,
                                     unsigned long long b) {
    asm("fma.rn.f32x2 %0, %1, %2, %0;" : "+l"(acc) : "l"(a), "l"(b));
}
__device__ __forceinline__ unsigned long long dup2(float x) {
    unsigned long long r;
    asm("mov.b64 %0, {%1, %1};" : "=l"(r) : "f"(x));
    return r;
}
__device__ __forceinline__ unsigned long long mul2(unsigned long long a,
                                                   unsigned long long b) {
    unsigned long long r;
    asm("mul.rn.f32x2 %0, %1, %2;" : "=l"(r) : "l"(a), "l"(b));
    return r;
}

// Lane p-block mapping: lane owns dims {p*128 + lane*4}, p=0..2 ->
// conflict-free LDS row slabs + coalesced STG.
__global__ __launch_bounds__(NWARPS * 32, 1)
void ge_main_kernel(const float* __restrict__ embed,
                    float* __restrict__ out, int Tt) {
    extern __shared__ float smem[];
    float* semb     = smem;                      // 153600 B, natural order
    float* s_center = semb + NVOCAB * ND;
    float* s_invsig = s_center + TC;
    float* s_wfac   = s_invsig + TC;
    int*   s_row    = (int*)(s_wfac + TC);
    int*   s_fidx   = s_row + TC;                // MAXT
    float* s_wbuf   = (float*)(s_fidx + MAXT);   // NWARPS * FB * WMAX
    int*   s_cbuf   = (int*)(s_wbuf + NWARPS * FB * WMAX); // NWARPS * WMAX

    int tid = threadIdx.x;
    int b = blockIdx.y;
    int totdur = g_totdur[b];

    {
        const float4* src = (const float4*)embed;
        float4* dst = (float4*)semb;
        for (int i = tid; i < NVOCAB * ND / 4; i += NWARPS * 32) dst[i] = src[i];
    }
    if (tid < TC) {
        s_center[tid] = g_center[b][tid];
        s_invsig[tid] = g_invsig[b][tid];
        s_wfac[tid]   = g_wfac[b][tid];
        s_row[tid]    = g_row[b][tid];
    }
    for (int f = tid; f < totdur; f += NWARPS * 32) s_fidx[f] = g_fidx[b][f];
    __syncthreads();

    int wid = tid >> 5, lane = tid & 31;
    float* wrow4 = s_wbuf + wid * (FB * WMAX);
    int*   coffw = s_cbuf + wid * WMAX;

    for (int t0 = (blockIdx.x * NWARPS + wid) * FB; t0 < Tt;
         t0 += NTILES * NWARPS * FB) {

        int nvalid = totdur - t0;
        if (nvalid > FB) nvalid = FB;

        if (nvalid <= 0) {                       // whole group time-pad -> embed[0]
            const float4* e = (const float4*)semb + lane;
            float4 e0 = e[0], e1 = e[32], e2 = e[64];
            #pragma unroll
            for (int f = 0; f < FB; f++) {
                int t = t0 + f;
                if (t >= Tt) break;
                float4* o = (float4*)(out + ((size_t)b * Tt + t) * ND) + lane;
                o[0] = e0; o[32] = e1; o[64] = e2;
            }
            continue;
        }

        int lo = s_fidx[max(t0 - RWIN, 0)];
        int hi = s_fidx[min(t0 + FB - 1 + RWIN, totdur - 1)] + 1;
        int win = hi - lo;

        // ---- weight pass (lane-parallel, raw weights) ----
        float tt = (float)t0 + 0.5f;
        float l0 = 0.f, l1 = 0.f, l2 = 0.f, l3 = 0.f;
        for (int j = lane; j < win; j += 32) {
            int c = lo + j;
            float is = s_invsig[c];
            float z0 = (tt - s_center[c]) * is;
            float z1 = z0 + is, z2 = z1 + is, z3 = z2 + is;
            float wf = s_wfac[c];
            float w0 = __expf(-0.5f * z0 * z0) * wf;
            float w1 = __expf(-0.5f * z1 * z1) * wf;
            float w2 = __expf(-0.5f * z2 * z2) * wf;
            float w3 = __expf(-0.5f * z3 * z3) * wf;
            if (1 >= nvalid) w1 = 0.f;
            if (2 >= nvalid) w2 = 0.f;
            if (3 >= nvalid) w3 = 0.f;
            *(float4*)&wrow4[j * 4] = make_float4(w0, w1, w2, w3);
            l0 += w0; l1 += w1; l2 += w2; l3 += w3;
        }
        __syncwarp();
        #pragma unroll
        for (int off = 16; off; off >>= 1) {
            l0 += __shfl_xor_sync(0xffffffffu, l0, off);
            l1 += __shfl_xor_sync(0xffffffffu, l1, off);
            l2 += __shfl_xor_sync(0xffffffffu, l2, off);
            l3 += __shfl_xor_sync(0xffffffffu, l3, off);
        }
        float i0 = 1.0f / (l0 + 1e-6f), i1 = 1.0f / (l1 + 1e-6f);
        float i2 = 1.0f / (l2 + 1e-6f), i3 = 1.0f / (l3 + 1e-6f);
        float th0 = 1e-8f * (l0 + 1e-6f), th1 = 1e-8f * (l1 + 1e-6f);
        float th2 = 1e-8f * (l2 + 1e-6f), th3 = 1e-8f * (l3 + 1e-6f);

        // ---- compact active chars ----
        int nact = 0;
        for (int base = 0; base < win; base += 32) {
            int j = base + lane;
            float4 wv;
            int off = 0;
            bool act = false;
            if (j < win) {
                wv = *(float4*)&wrow4[j * 4];
                act = (wv.x > th0) | (wv.y > th1) | (wv.z > th2) | (wv.w > th3);
                off = s_row[lo + j] * ND;
            }
            unsigned mask = __ballot_sync(0xffffffffu, act);
            __syncwarp();
            if (act) {
                int pos = nact + __popc(mask & ((1u << lane) - 1u));
                *(float4*)&wrow4[pos * 4] = wv;   // pos <= j, no clobber
                coffw[pos] = off;
            }
            nact += __popc(mask);
        }
        __syncwarp();

        // ---- software-pipelined branch-free FMA pass ----
        unsigned long long A[FB][6];
        #pragma unroll
        for (int f = 0; f < FB; f++)
            #pragma unroll
            for (int k = 0; k < 6; k++) A[f][k] = 0ULL;

        {
            // prologue: load iteration 0
            float4 wv = *(float4*)&wrow4[0];
            const ulonglong2* e = (const ulonglong2*)(semb + coffw[0]) + lane;
            ulonglong2 p0 = e[0], p1 = e[32], p2 = e[64];

            for (int k = 0; k < nact; k++) {
                // consume-copy (register rename), then prefetch k+1
                float4 wc = wv;
                ulonglong2 q0 = p0, q1 = p1, q2 = p2;
                int kn = (k + 1 < nact) ? k + 1 : k;
                wv = *(float4*)&wrow4[kn * 4];
                e = (const ulonglong2*)(semb + coffw[kn]) + lane;
                p0 = e[0]; p1 = e[32]; p2 = e[64];

                unsigned long long W0 = dup2(wc.x), W1 = dup2(wc.y);
                unsigned long long W2 = dup2(wc.z), W3 = dup2(wc.w);
                fma2(A[0][0], W0, q0.x); fma2(A[0][1], W0, q0.y);
                fma2(A[0][2], W0, q1.x); fma2(A[0][3], W0, q1.y);
                fma2(A[0][4], W0, q2.x); fma2(A[0][5], W0, q2.y);
                fma2(A[1][0], W1, q0.x); fma2(A[1][1], W1, q0.y);
                fma2(A[1][2], W1, q1.x); fma2(A[1][3], W1, q1.y);
                fma2(A[1][4], W1, q2.x); fma2(A[1][5], W1, q2.y);
                fma2(A[2][0], W2, q0.x); fma2(A[2][1], W2, q0.y);
                fma2(A[2][2], W2, q1.x); fma2(A[2][3], W2, q1.y);
                fma2(A[2][4], W2, q2.x); fma2(A[2][5], W2, q2.y);
                fma2(A[3][0], W3, q0.x); fma2(A[3][1], W3, q0.y);
                fma2(A[3][2], W3, q1.x); fma2(A[3][3], W3, q1.y);
                fma2(A[3][4], W3, q2.x); fma2(A[3][5], W3, q2.y);
            }
        }
        __syncwarp();   // wrow4/coffw reused next group

        // ---- scale by 1/sum and write (coalesced) ----
        unsigned long long I[FB] = { dup2(i0), dup2(i1), dup2(i2), dup2(i3) };
        #pragma unroll
        for (int f = 0; f < FB; f++) {
            int t = t0 + f;
            if (t >= Tt) break;
            float4* o = (float4*)(out + ((size_t)b * Tt + t) * ND) + lane;
            if (f < nvalid) {
                union { unsigned long long u[2]; float4 v; } cv;
                cv.u[0] = mul2(A[f][0], I[f]); cv.u[1] = mul2(A[f][1], I[f]); o[0]  = cv.v;
                cv.u[0] = mul2(A[f][2], I[f]); cv.u[1] = mul2(A[f][3], I[f]); o[32] = cv.v;
                cv.u[0] = mul2(A[f][4], I[f]); cv.u[1] = mul2(A[f][5], I[f]); o[64] = cv.v;
            } else {    // time-pad frame -> embed[0]
                const float4* e = (const float4*)semb + lane;
                o[0] = e[0]; o[32] = e[32]; o[64] = e[64];
            }
        }
    }
}

extern "C" void kernel_launch(void* const* d_in, const int* in_sizes, int n_in,
                              void* d_out, int out_size) {
    const int*   text  = (const int*)d_in[0];
    const int*   durs  = (const int*)d_in[1];
    const float* embed = (const float*)d_in[2];
    float* out = (float*)d_out;

    int Tt = out_size / (NB * ND);

    size_t smem_bytes = (size_t)(NVOCAB * ND + 3 * TC) * sizeof(float)
                        + (size_t)(TC + MAXT) * sizeof(int)
                        + (size_t)(NWARPS * FB * WMAX) * sizeof(float)
                        + (size_t)(NWARPS * WMAX) * sizeof(int);
    cudaFuncSetAttribute(ge_main_kernel,
                         cudaFuncAttributeMaxDynamicSharedMemorySize,
                         (int)smem_bytes);

    ge_prep_kernel<<<NB, TC>>>(text, durs);
    ge_main_kernel<<<dim3(NTILES, NB), NWARPS * 32, smem_bytes>>>(embed, out, Tt);
}

// round 8
// speedup vs baseline: 1.0906x; 1.0906x over previous
#include <cuda_runtime.h>
#include <cuda_bf16.h>

#define NB 32
#define TC 256
#define NVOCAB 100
#define ND 384
#define DCH 128          // dims per block (3-way D split)
#define NWARPS 16
#define NTILES 3
#define MAXT 2048
#define FB 4             // frames per warp per group
#define RWIN 32          // |t-center|>RWIN => z>=8 => rel contribution < 1e-13
#define WMAX 72          // max chars in union window ((FB-1)+2*RWIN+1 = 68)

__device__ float g_center[NB][TC];
__device__ float g_invsig[NB][TC];
__device__ float g_wfac[NB][TC];
__device__ int   g_row[NB][TC];
__device__ int   g_totdur[NB];
__device__ int   g_fidx[NB][MAXT];

__global__ void ge_prep_kernel(const int* __restrict__ text,
                               const int* __restrict__ durs) {
    __shared__ int s[TC];
    int b = blockIdx.x, c = threadIdx.x;
    int d = durs[b * TC + c];
    s[c] = d;
    __syncthreads();
    #pragma unroll
    for (int off = 1; off < TC; off <<= 1) {
        int v = (c >= off) ? s[c - off] : 0;
        __syncthreads();
        s[c] += v;
        __syncthreads();
    }
    int incl = s[c];
    int start = incl - d;
    float df = (float)d;
    float sig = df * 0.5f + 1e-6f;
    float is = 1.0f / sig;
    g_center[b][c] = (float)start + df * 0.5f;
    g_invsig[b][c] = is;
    g_wfac[b][c]   = 0.3989422804014327f * is;
    g_row[b][c]    = text[b * TC + c];
    for (int f = start; f < incl; f++) g_fidx[b][f] = c;
    if (c == TC - 1) g_totdur[b] = incl;
}

__device__ __forceinline__ void fma2(unsigned long long& acc,
                                     unsigned long long a,
                                     unsigned long long b) {
    asm("fma.rn.f32x2 %0, %1, %2, %0;" : "+l"(acc) : "l"(a), "l"(b));
}
__device__ __forceinline__ unsigned long long dup2(float x) {
    unsigned long long r;
    asm("mov.b64 %0, {%1, %1};" : "=l"(r) : "f"(x));
    return r;
}
__device__ __forceinline__ unsigned long long mul2(unsigned long long a,
                                                   unsigned long long b) {
    unsigned long long r;
    asm("mul.rn.f32x2 %0, %1, %2;" : "=l"(r) : "l"(a), "l"(b));
    return r;
}

// 3-way D split: block (bx, b, h) covers dims [h*128, (h+1)*128).
// Lane owns float4 at h*128 + lane*4: conflict-free LDS, coalesced STG.
__global__ __launch_bounds__(NWARPS * 32, 2)
void ge_main_kernel(const float* __restrict__ embed,
                    float* __restrict__ out, int Tt) {
    extern __shared__ float smem[];
    float* semb     = smem;                      // NVOCAB*DCH floats (51200 B)
    float* s_center = semb + NVOCAB * DCH;       // 256
    float* s_invsig = s_center + TC;             // 256
    float* s_wfac   = s_invsig + TC;             // 256
    int*   s_roff   = (int*)(s_wfac + TC);       // 256 (row*DCH)
    int*   s_fidx   = s_roff + TC;               // MAXT
    float* s_wbuf   = (float*)(s_fidx + MAXT);   // NWARPS*FB*WMAX
    int*   s_cbuf   = (int*)(s_wbuf + NWARPS * FB * WMAX); // NWARPS*WMAX

    int tid = threadIdx.x;
    int b = blockIdx.y;
    int h = blockIdx.z;
    int totdur = g_totdur[b];

    // Stage the 128-dim slab of the table: row v -> semb[v*DCH ...]
    {
        // thread i handles (v, c): one float4 from embed[v*ND + h*DCH + c*4]
        for (int i = tid; i < NVOCAB * 32; i += NWARPS * 32) {
            int v = i >> 5, c = i & 31;
            ((float4*)(semb + v * DCH))[c] =
                *((const float4*)(embed + v * ND + h * DCH) + c);
        }
    }
    if (tid < TC) {
        s_center[tid] = g_center[b][tid];
        s_invsig[tid] = g_invsig[b][tid];
        s_wfac[tid]   = g_wfac[b][tid];
        s_roff[tid]   = g_row[b][tid] * DCH;
    }
    for (int f = tid; f < totdur; f += NWARPS * 32) s_fidx[f] = g_fidx[b][f];
    __syncthreads();

    int wid = tid >> 5, lane = tid & 31;
    float* wrow4 = s_wbuf + wid * (FB * WMAX);
    int*   coffw = s_cbuf + wid * WMAX;

    for (int t0 = (blockIdx.x * NWARPS + wid) * FB; t0 < Tt;
         t0 += NTILES * NWARPS * FB) {

        int nvalid = totdur - t0;
        if (nvalid > FB) nvalid = FB;

        if (nvalid <= 0) {                       // whole group time-pad -> embed[0]
            float4 e0 = ((const float4*)semb)[lane];
            #pragma unroll
            for (int f = 0; f < FB; f++) {
                int t = t0 + f;
                if (t >= Tt) break;
                ((float4*)(out + ((size_t)b * Tt + t) * ND + h * DCH))[lane] = e0;
            }
            continue;
        }

        int lo = s_fidx[max(t0 - RWIN, 0)];
        int hi = s_fidx[min(t0 + FB - 1 + RWIN, totdur - 1)] + 1;
        int win = hi - lo;

        // ---- weight pass (lane-parallel, raw weights) ----
        float tt = (float)t0 + 0.5f;
        float l0 = 0.f, l1 = 0.f, l2 = 0.f, l3 = 0.f;
        for (int j = lane; j < win; j += 32) {
            int c = lo + j;
            float is = s_invsig[c];
            float z0 = (tt - s_center[c]) * is;
            float z1 = z0 + is, z2 = z1 + is, z3 = z2 + is;
            float wf = s_wfac[c];
            float w0 = __expf(-0.5f * z0 * z0) * wf;
            float w1 = __expf(-0.5f * z1 * z1) * wf;
            float w2 = __expf(-0.5f * z2 * z2) * wf;
            float w3 = __expf(-0.5f * z3 * z3) * wf;
            if (1 >= nvalid) w1 = 0.f;
            if (2 >= nvalid) w2 = 0.f;
            if (3 >= nvalid) w3 = 0.f;
            *(float4*)&wrow4[j * 4] = make_float4(w0, w1, w2, w3);
            l0 += w0; l1 += w1; l2 += w2; l3 += w3;
        }
        __syncwarp();
        #pragma unroll
        for (int off = 16; off; off >>= 1) {
            l0 += __shfl_xor_sync(0xffffffffu, l0, off);
            l1 += __shfl_xor_sync(0xffffffffu, l1, off);
            l2 += __shfl_xor_sync(0xffffffffu, l2, off);
            l3 += __shfl_xor_sync(0xffffffffu, l3, off);
        }
        float i0 = 1.0f / (l0 + 1e-6f), i1 = 1.0f / (l1 + 1e-6f);
        float i2 = 1.0f / (l2 + 1e-6f), i3 = 1.0f / (l3 + 1e-6f);
        float th0 = 1e-8f * (l0 + 1e-6f), th1 = 1e-8f * (l1 + 1e-6f);
        float th2 = 1e-8f * (l2 + 1e-6f), th3 = 1e-8f * (l3 + 1e-6f);

        // ---- compact active chars ----
        int nact = 0;
        for (int base = 0; base < win; base += 32) {
            int j = base + lane;
            float4 wv;
            int off = 0;
            bool act = false;
            if (j < win) {
                wv = *(float4*)&wrow4[j * 4];
                act = (wv.x > th0) | (wv.y > th1) | (wv.z > th2) | (wv.w > th3);
                off = s_roff[lo + j];
            }
            unsigned mask = __ballot_sync(0xffffffffu, act);
            __syncwarp();
            if (act) {
                int pos = nact + __popc(mask & ((1u << lane) - 1u));
                *(float4*)&wrow4[pos * 4] = wv;   // pos <= j, no clobber
                coffw[pos] = off;
            }
            nact += __popc(mask);
        }
        __syncwarp();

        // ---- branch-free FMA pass: one LDS.128 slab per char ----
        unsigned long long A[FB][2];
        #pragma unroll
        for (int f = 0; f < FB; f++) { A[f][0] = 0ULL; A[f][1] = 0ULL; }

        for (int k = 0; k < nact; k++) {
            float4 wv = *(float4*)&wrow4[k * 4];      // LDS.128 broadcast
            int off = coffw[k];                        // LDS broadcast
            ulonglong2 p = ((const ulonglong2*)(semb + off))[lane];
            unsigned long long W0 = dup2(wv.x), W1 = dup2(wv.y);
            unsigned long long W2 = dup2(wv.z), W3 = dup2(wv.w);
            fma2(A[0][0], W0, p.x); fma2(A[0][1], W0, p.y);
            fma2(A[1][0], W1, p.x); fma2(A[1][1], W1, p.y);
            fma2(A[2][0], W2, p.x); fma2(A[2][1], W2, p.y);
            fma2(A[3][0], W3, p.x); fma2(A[3][1], W3, p.y);
        }
        __syncwarp();   // wrow4/coffw reused next group

        // ---- scale by 1/sum and write (coalesced 512B) ----
        unsigned long long I[FB] = { dup2(i0), dup2(i1), dup2(i2), dup2(i3) };
        #pragma unroll
        for (int f = 0; f < FB; f++) {
            int t = t0 + f;
            if (t >= Tt) break;
            float4* o = (float4*)(out + ((size_t)b * Tt + t) * ND + h * DCH);
            if (f < nvalid) {
                union { unsigned long long u[2]; float4 v; } cv;
                cv.u[0] = mul2(A[f][0], I[f]);
                cv.u[1] = mul2(A[f][1], I[f]);
                o[lane] = cv.v;
            } else {    // time-pad frame -> embed[0]
                o[lane] = ((const float4*)semb)[lane];
            }
        }
    }
}

extern "C" void kernel_launch(void* const* d_in, const int* in_sizes, int n_in,
                              void* d_out, int out_size) {
    const int*   text  = (const int*)d_in[0];
    const int*   durs  = (const int*)d_in[1];
    const float* embed = (const float*)d_in[2];
    float* out = (float*)d_out;

    int Tt = out_size / (NB * ND);

    size_t smem_bytes = (size_t)(NVOCAB * DCH + 3 * TC) * sizeof(float)
                        + (size_t)(TC + MAXT) * sizeof(int)
                        + (size_t)(NWARPS * FB * WMAX) * sizeof(float)
                        + (size_t)(NWARPS * WMAX) * sizeof(int);
    cudaFuncSetAttribute(ge_main_kernel,
                         cudaFuncAttributeMaxDynamicSharedMemorySize,
                         (int)smem_bytes);

    ge_prep_kernel<<<NB, TC>>>(text, durs);
    ge_main_kernel<<<dim3(NTILES, NB, 3), NWARPS * 32, smem_bytes>>>(embed, out, Tt);
}